// round 4
// baseline (speedup 1.0000x reference)
#include <cuda_runtime.h>
#include <math.h>

#define HID 128
#define NG  50

typedef unsigned long long u64;

// Scratch (static device arrays — allocation is forbidden)
__device__ float g_h  [40000 * 128];
__device__ float g_agg[40000 * 128];
__device__ float g_h2 [40000 * 128];

// fast shifted-softplus: ssp(x) = LN2*(max(t,0) + lg2(1+2^-|t|)) - LN2, t = x*log2(e)
__device__ __forceinline__ float sspf(float x) {
    const float LOG2E = 1.4426950408889634f;
    const float LN2   = 0.69314718055994530942f;
    float t = x * LOG2E;
    float e; asm("ex2.approx.f32 %0, %1;" : "=f"(e) : "f"(-fabsf(t)));
    float l; asm("lg2.approx.f32 %0, %1;" : "=f"(l) : "f"(1.f + e));
    return fmaf(LN2, fmaxf(t, 0.f) + l, -LN2);
}

// ---- packed fp32x2 helpers ----
__device__ __forceinline__ u64 dup2(float v) {
    u64 r; asm("mov.b64 %0, {%1,%2};" : "=l"(r) : "f"(v), "f"(v)); return r;
}
__device__ __forceinline__ u64 fma2(u64 a, u64 b, u64 c) {
    u64 d; asm("fma.rn.f32x2 %0, %1, %2, %3;" : "=l"(d) : "l"(a), "l"(b), "l"(c)); return d;
}
__device__ __forceinline__ float2 unp2(u64 v) {
    float lo, hi; asm("mov.b64 {%0,%1}, %2;" : "=f"(lo), "=f"(hi) : "l"(v));
    return make_float2(lo, hi);
}
__device__ __forceinline__ void red4(float* p, float a, float b, float c, float d) {
    asm volatile("red.global.add.v4.f32 [%0], {%1,%2,%3,%4};"
                 :: "l"(p), "f"(a), "f"(b), "f"(c), "f"(d) : "memory");
}

// ---------------------------------------------------------------------------
// Node GEMM: C[M,128] = act(A @ W^T + bias). 64-row tiles, 256 threads,
// 4x8 microtile, 2 CTAs/SM (smem ~101KB).
// ---------------------------------------------------------------------------
__global__ __launch_bounds__(256, 2) void gemm128_kernel(
    const float* __restrict__ A, const float* __restrict__ W,
    const float* __restrict__ bias, float* __restrict__ C,
    int M, int act, float* __restrict__ zbuf)
{
    extern __shared__ float sm[];
    float (*sA)[132] = (float(*)[132])(sm);              // 64 x 132
    float (*sB)[132] = (float(*)[132])(sm + 64 * 132);   // 128 x 132

    const int tid  = threadIdx.x;
    const int row0 = blockIdx.x * 64;

    for (int idx = tid; idx < 128 * 128; idx += 256) {
        int k = idx & 127, f = idx >> 7;
        sB[k][f] = W[idx];
    }
    for (int idx = tid; idx < 64 * 128; idx += 256) {
        int k = idx & 127, r = idx >> 7;
        int gr = row0 + r;
        sA[r][k] = (gr < M) ? A[(size_t)gr * 128 + k] : 0.f;
    }
    __syncthreads();

    const int tx = tid & 15;   // 8-feature group
    const int ty = tid >> 4;   // 0..15, 4 rows each

    u64 acc[4][4];
    #pragma unroll
    for (int i = 0; i < 4; i++)
        #pragma unroll
        for (int j = 0; j < 4; j++) acc[i][j] = 0ull;

    #pragma unroll 4
    for (int k = 0; k < 128; ++k) {
        u64 ad[4];
        #pragma unroll
        for (int i = 0; i < 4; i++) ad[i] = dup2(sA[ty * 4 + i][k]);
        ulonglong2 q0 = *reinterpret_cast<const ulonglong2*>(&sB[k][tx * 8]);
        ulonglong2 q1 = *reinterpret_cast<const ulonglong2*>(&sB[k][tx * 8 + 4]);
        u64 bp[4] = {q0.x, q0.y, q1.x, q1.y};
        #pragma unroll
        for (int i = 0; i < 4; i++)
            #pragma unroll
            for (int j = 0; j < 4; j++)
                acc[i][j] = fma2(ad[i], bp[j], acc[i][j]);
    }

    float bb[8];
    if (bias) {
        float4 c0 = *reinterpret_cast<const float4*>(bias + tx * 8);
        float4 c1 = *reinterpret_cast<const float4*>(bias + tx * 8 + 4);
        bb[0]=c0.x; bb[1]=c0.y; bb[2]=c0.z; bb[3]=c0.w;
        bb[4]=c1.x; bb[5]=c1.y; bb[6]=c1.z; bb[7]=c1.w;
    } else {
        #pragma unroll
        for (int j = 0; j < 8; j++) bb[j] = 0.f;
    }

    #pragma unroll
    for (int i = 0; i < 4; i++) {
        int r = row0 + ty * 4 + i;
        if (r < M) {
            float v[8];
            #pragma unroll
            for (int j = 0; j < 4; j++) {
                float2 p = unp2(acc[i][j]);
                float t0 = p.x + bb[2*j], t1 = p.y + bb[2*j+1];
                v[2*j]   = act ? sspf(t0) : t0;
                v[2*j+1] = act ? sspf(t1) : t1;
            }
            float4* cp = reinterpret_cast<float4*>(C + (size_t)r * 128 + tx * 8);
            cp[0] = make_float4(v[0], v[1], v[2], v[3]);
            cp[1] = make_float4(v[4], v[5], v[6], v[7]);
            if (zbuf) {
                float4* zp = reinterpret_cast<float4*>(zbuf + (size_t)r * 128 + tx * 8);
                zp[0] = make_float4(0.f, 0.f, 0.f, 0.f);
                zp[1] = make_float4(0.f, 0.f, 0.f, 0.f);
            }
        }
    }
}

// ---------------------------------------------------------------------------
// Persistent fused edge kernel, 512 threads (16 warps), 4x8 microtile.
// Weights staged in smem once per block; loop over 128-edge tiles.
// ---------------------------------------------------------------------------
__global__ __launch_bounds__(512, 1) void edge_kernel(
    const float* __restrict__ ea, const int* __restrict__ ei,
    const float* __restrict__ ew,
    const float* __restrict__ w1, const float* __restrict__ b1,
    const float* __restrict__ w2, const float* __restrict__ b2,
    const float* __restrict__ h,  float* __restrict__ agg,
    int E, int nTiles)
{
    extern __shared__ float sm[];
    float (*sEA)[52]  = (float(*)[52])(sm);                         // 128*52
    float (*sW1)[132] = (float(*)[132])(sm + 6656);                 // 50*132
    float (*sW2)[132] = (float(*)[132])(sm + 6656 + 6600);          // 128*132
    float (*sT)[132]  = (float(*)[132])(sm + 6656 + 6600 + 16896);  // 128*132
    float* sC   = sm + 6656 + 6600 + 16896 + 16896;
    int*   sSrc = (int*)(sC + 128);
    int*   sDst = sSrc + 128;

    const int tid = threadIdx.x;
    const int tx  = tid & 15;   // 8-feature group
    const int ty  = tid >> 4;   // 0..31, 4 edges each

    // ---- one-time weight staging (k-major) ----
    for (int idx = tid; idx < 128 * NG; idx += 512) {
        int g = idx % NG, f = idx / NG;
        sW1[g][f] = w1[idx];
    }
    for (int idx = tid; idx < 128 * 128; idx += 512) {
        int k = idx & 127, f = idx >> 7;
        sW2[k][f] = w2[idx];
    }

    float bb1[8], bb2[8];
    {
        float4 c0 = *reinterpret_cast<const float4*>(b1 + tx * 8);
        float4 c1 = *reinterpret_cast<const float4*>(b1 + tx * 8 + 4);
        bb1[0]=c0.x; bb1[1]=c0.y; bb1[2]=c0.z; bb1[3]=c0.w;
        bb1[4]=c1.x; bb1[5]=c1.y; bb1[6]=c1.z; bb1[7]=c1.w;
        float4 d0 = *reinterpret_cast<const float4*>(b2 + tx * 8);
        float4 d1 = *reinterpret_cast<const float4*>(b2 + tx * 8 + 4);
        bb2[0]=d0.x; bb2[1]=d0.y; bb2[2]=d0.z; bb2[3]=d0.w;
        bb2[4]=d1.x; bb2[5]=d1.y; bb2[6]=d1.z; bb2[7]=d1.w;
    }

    for (int t = blockIdx.x; t < nTiles; t += gridDim.x) {
        const int e0 = t * 128;

        // ---- tile staging ----
        if (tid < 128) {
            int e = e0 + tid;
            if (e < E) {
                sSrc[tid] = ei[e];
                sDst[tid] = ei[E + e];
                sC[tid] = 0.5f * (__cosf(ew[e] * 0.31415926535897932f) + 1.f);
            } else { sSrc[tid] = 0; sDst[tid] = 0; sC[tid] = 0.f; }
        }
        for (int idx = tid; idx < 128 * NG; idx += 512) {
            int g = idx % NG, e = idx / NG;
            sEA[e][g] = (e0 + e < E) ? ea[(size_t)e0 * NG + idx] : 0.f;
        }
        __syncthreads();

        // ---- GEMM1: T = ssp(EA @ w1^T + b1), K = 50 ----
        u64 acc[4][4];
        #pragma unroll
        for (int i = 0; i < 4; i++)
            #pragma unroll
            for (int j = 0; j < 4; j++) acc[i][j] = 0ull;

        #pragma unroll 2
        for (int k = 0; k < NG; ++k) {
            u64 ad[4];
            #pragma unroll
            for (int i = 0; i < 4; i++) ad[i] = dup2(sEA[ty * 4 + i][k]);
            ulonglong2 q0 = *reinterpret_cast<const ulonglong2*>(&sW1[k][tx * 8]);
            ulonglong2 q1 = *reinterpret_cast<const ulonglong2*>(&sW1[k][tx * 8 + 4]);
            u64 bp[4] = {q0.x, q0.y, q1.x, q1.y};
            #pragma unroll
            for (int i = 0; i < 4; i++)
                #pragma unroll
                for (int j = 0; j < 4; j++)
                    acc[i][j] = fma2(ad[i], bp[j], acc[i][j]);
        }

        #pragma unroll
        for (int i = 0; i < 4; i++) {
            float v[8];
            #pragma unroll
            for (int j = 0; j < 4; j++) {
                float2 p = unp2(acc[i][j]);
                v[2*j]   = sspf(p.x + bb1[2*j]);
                v[2*j+1] = sspf(p.y + bb1[2*j+1]);
            }
            float4* tp = reinterpret_cast<float4*>(&sT[ty * 4 + i][tx * 8]);
            tp[0] = make_float4(v[0], v[1], v[2], v[3]);
            tp[1] = make_float4(v[4], v[5], v[6], v[7]);
        }
        __syncthreads();

        // ---- GEMM2: Wf = T @ w2^T + b2, K = 128 ----
        #pragma unroll
        for (int i = 0; i < 4; i++)
            #pragma unroll
            for (int j = 0; j < 4; j++) acc[i][j] = 0ull;

        #pragma unroll 4
        for (int k = 0; k < 128; ++k) {
            u64 ad[4];
            #pragma unroll
            for (int i = 0; i < 4; i++) ad[i] = dup2(sT[ty * 4 + i][k]);
            ulonglong2 q0 = *reinterpret_cast<const ulonglong2*>(&sW2[k][tx * 8]);
            ulonglong2 q1 = *reinterpret_cast<const ulonglong2*>(&sW2[k][tx * 8 + 4]);
            u64 bp[4] = {q0.x, q0.y, q1.x, q1.y};
            #pragma unroll
            for (int i = 0; i < 4; i++)
                #pragma unroll
                for (int j = 0; j < 4; j++)
                    acc[i][j] = fma2(ad[i], bp[j], acc[i][j]);
        }

        // ---- epilogue: cutoff * gather(h[src]) -> red.v4 into agg[dst] ----
        #pragma unroll
        for (int i = 0; i < 4; i++) {
            int e = ty * 4 + i;
            if (e0 + e >= E) continue;
            int   s = sSrc[e];
            int   d = sDst[e];
            float c = sC[e];
            const float4* hp = reinterpret_cast<const float4*>(h + (size_t)s * 128 + tx * 8);
            float4 h0 = hp[0];
            float4 h1 = hp[1];
            float* ap = agg + (size_t)d * 128 + tx * 8;
            float2 p0 = unp2(acc[i][0]), p1 = unp2(acc[i][1]);
            float2 p2 = unp2(acc[i][2]), p3 = unp2(acc[i][3]);
            red4(ap,     (p0.x + bb2[0]) * c * h0.x, (p0.y + bb2[1]) * c * h0.y,
                         (p1.x + bb2[2]) * c * h0.z, (p1.y + bb2[3]) * c * h0.w);
            red4(ap + 4, (p2.x + bb2[4]) * c * h1.x, (p2.y + bb2[5]) * c * h1.y,
                         (p3.x + bb2[6]) * c * h1.z, (p3.y + bb2[7]) * c * h1.w);
        }
        __syncthreads();
    }
}

// ---------------------------------------------------------------------------
extern "C" void kernel_launch(void* const* d_in, const int* in_sizes, int n_in,
                              void* d_out, int out_size)
{
    const float* x   = (const float*)d_in[0];
    const int*   ei  = (const int*)  d_in[1];
    const float* ew  = (const float*)d_in[2];
    const float* ea  = (const float*)d_in[3];
    const float* mw1 = (const float*)d_in[4];
    const float* mb1 = (const float*)d_in[5];
    const float* mw2 = (const float*)d_in[6];
    const float* mb2 = (const float*)d_in[7];
    const float* l1w = (const float*)d_in[8];
    const float* l2w = (const float*)d_in[9];
    const float* l2b = (const float*)d_in[10];
    const float* lw  = (const float*)d_in[11];
    const float* lb  = (const float*)d_in[12];
    float* out = (float*)d_out;

    const int N = in_sizes[0] / 128;
    const int E = in_sizes[1] / 2;

    void* p;
    cudaGetSymbolAddress(&p, g_h);   float* h_buf   = (float*)p;
    cudaGetSymbolAddress(&p, g_agg); float* agg_buf = (float*)p;
    cudaGetSymbolAddress(&p, g_h2);  float* h2_buf  = (float*)p;

    int sms = 148;
    cudaDeviceGetAttribute(&sms, cudaDevAttrMultiProcessorCount, 0);

    const size_t smemG = (size_t)(64 + 128) * 132 * sizeof(float);            // ~101 KB
    const size_t smemE = (size_t)(6656 + 6600 + 16896 + 16896 + 128) * 4 + 256 * 4;

    cudaFuncSetAttribute(gemm128_kernel, cudaFuncAttributeMaxDynamicSharedMemorySize, (int)smemG);
    cudaFuncSetAttribute(edge_kernel,    cudaFuncAttributeMaxDynamicSharedMemorySize, (int)smemE);

    const int nb     = (N + 63) / 64;        // 625
    const int nTiles = (E + 127) / 128;      // 5000

    gemm128_kernel<<<nb, 256, smemG>>>(x, l1w, nullptr, h_buf, N, 0, agg_buf);
    edge_kernel<<<sms, 512, smemE>>>(ea, ei, ew, mw1, mb1, mw2, mb2, h_buf, agg_buf, E, nTiles);
    gemm128_kernel<<<nb, 256, smemG>>>(agg_buf, l2w, l2b, h2_buf, N, 1, nullptr);
    gemm128_kernel<<<nb, 256, smemG>>>(h2_buf, lw, lb, out, N, 0, nullptr);
}

// round 11
// speedup vs baseline: 1.8998x; 1.8998x over previous
#include <cuda_runtime.h>
#include <cuda_bf16.h>
#include <math.h>

#define NG 50
typedef unsigned int u32;
typedef unsigned long long u64;

// ---- scratch (allocation forbidden) ----
__device__ float g_h  [40000 * 128];
__device__ float g_agg[40000 * 128];
__device__ float g_h2 [40000 * 128];

// ---- fast shifted softplus ----
__device__ __forceinline__ float sspf(float x) {
    const float LOG2E = 1.4426950408889634f;
    const float LN2   = 0.69314718055994530942f;
    float t = x * LOG2E;
    float e; asm("ex2.approx.f32 %0, %1;" : "=f"(e) : "f"(-fabsf(t)));
    float l; asm("lg2.approx.f32 %0, %1;" : "=f"(l) : "f"(1.f + e));
    return fmaf(LN2, fmaxf(t, 0.f) + l, -LN2);
}

// ---- packed fp32x2 (node GEMMs) ----
__device__ __forceinline__ u64 dup2(float v) {
    u64 r; asm("mov.b64 %0, {%1,%2};" : "=l"(r) : "f"(v), "f"(v)); return r;
}
__device__ __forceinline__ u64 fma2(u64 a, u64 b, u64 c) {
    u64 d; asm("fma.rn.f32x2 %0, %1, %2, %3;" : "=l"(d) : "l"(a), "l"(b), "l"(c)); return d;
}
__device__ __forceinline__ float2 unp2(u64 v) {
    float lo, hi; asm("mov.b64 {%0,%1}, %2;" : "=f"(lo), "=f"(hi) : "l"(v));
    return make_float2(lo, hi);
}
__device__ __forceinline__ void red4(float* p, float a, float b, float c, float d) {
    asm volatile("red.global.add.v4.f32 [%0], {%1,%2,%3,%4};"
                 :: "l"(p), "f"(a), "f"(b), "f"(c), "f"(d) : "memory");
}

// ---- bf16 pack/split ----
__device__ __forceinline__ u32 pack2bf(float v0, float v1) {
    u32 r; asm("cvt.rn.bf16x2.f32 %0, %1, %2;" : "=r"(r) : "f"(v1), "f"(v0)); return r;
}
__device__ __forceinline__ float bf_lo(u32 w) {
    return __bfloat162float(__ushort_as_bfloat16((unsigned short)(w & 0xFFFF)));
}
__device__ __forceinline__ float bf_hi(u32 w) {
    return __bfloat162float(__ushort_as_bfloat16((unsigned short)(w >> 16)));
}
__device__ __forceinline__ void split2(float v0, float v1, u32& hiw, u32& low) {
    hiw = pack2bf(v0, v1);
    low = pack2bf(v0 - bf_lo(hiw), v1 - bf_hi(hiw));
}

// ---- ldmatrix / mma ----
// A: [m][k] row-major -> ldmatrix no-trans.
// B: [n][k] row-major == col-major k x n -> ldmatrix NO-trans (trans was the bug).
#define LDSM_X4(R, ADDR) \
    asm volatile("ldmatrix.sync.aligned.m8n8.x4.shared.b16 {%0,%1,%2,%3}, [%4];" \
        : "=r"((R)[0]), "=r"((R)[1]), "=r"((R)[2]), "=r"((R)[3]) : "r"(ADDR))
#define MMA16816(D, A, B0, B1) \
    asm volatile("mma.sync.aligned.m16n8k16.row.col.f32.bf16.bf16.f32 " \
        "{%0,%1,%2,%3},{%4,%5,%6,%7},{%8,%9},{%0,%1,%2,%3};" \
        : "+f"((D)[0]), "+f"((D)[1]), "+f"((D)[2]), "+f"((D)[3]) \
        : "r"((A)[0]), "r"((A)[1]), "r"((A)[2]), "r"((A)[3]), "r"(B0), "r"(B1))

// smem byte offsets (edge kernel)
#define OFF_W1HI 0
#define OFF_W1LO 18432
#define OFF_W2HI 36864
#define OFF_W2LO 71680
#define OFF_EAHI 106496
#define OFF_EALO 124928
#define OFF_THI  143360
#define OFF_TLO  161792
#define OFF_D    106496          /* fp32 [128][132], reuses EA+T region */
#define OFF_B1   180224
#define OFF_C    180736
#define OFF_SRC  181248
#define OFF_DST  181760
#define SMEM_EDGE 182272
// row strides (bytes): EA/W1/T = 144 (72 halves), W2 = 272 (136 halves), D = 528 (132 floats)

// ---------------------------------------------------------------------------
// Node GEMM (proven config): C = act(A @ W^T + bias), fp32x2 math.
// ---------------------------------------------------------------------------
__global__ __launch_bounds__(256, 1) void gemm128_kernel(
    const float* __restrict__ A, const float* __restrict__ W,
    const float* __restrict__ bias, float* __restrict__ C,
    int M, int act, float* __restrict__ zbuf)
{
    extern __shared__ float sm[];
    float (*sA)[132] = (float(*)[132])(sm);
    float (*sB)[132] = (float(*)[132])(sm + 128 * 132);

    const int tid  = threadIdx.x;
    const int row0 = blockIdx.x * 128;

    for (int idx = tid; idx < 128 * 128; idx += 256) {
        int k = idx & 127, f = idx >> 7;
        sB[k][f] = W[idx];
    }
    for (int idx = tid; idx < 128 * 128; idx += 256) {
        int k = idx & 127, r = idx >> 7;
        int gr = row0 + r;
        sA[r][k] = (gr < M) ? A[(size_t)gr * 128 + k] : 0.f;
    }
    __syncthreads();

    const int tx = tid & 15;
    const int ty = tid >> 4;

    u64 acc[8][4];
    #pragma unroll
    for (int i = 0; i < 8; i++)
        #pragma unroll
        for (int j = 0; j < 4; j++) acc[i][j] = 0ull;

    #pragma unroll 4
    for (int k = 0; k < 128; ++k) {
        u64 ad[8];
        #pragma unroll
        for (int i = 0; i < 8; i++) ad[i] = dup2(sA[ty * 8 + i][k]);
        ulonglong2 q0 = *reinterpret_cast<const ulonglong2*>(&sB[k][tx * 8]);
        ulonglong2 q1 = *reinterpret_cast<const ulonglong2*>(&sB[k][tx * 8 + 4]);
        u64 bp[4] = {q0.x, q0.y, q1.x, q1.y};
        #pragma unroll
        for (int i = 0; i < 8; i++)
            #pragma unroll
            for (int j = 0; j < 4; j++)
                acc[i][j] = fma2(ad[i], bp[j], acc[i][j]);
    }

    float bb[8];
    if (bias) {
        float4 c0 = *reinterpret_cast<const float4*>(bias + tx * 8);
        float4 c1 = *reinterpret_cast<const float4*>(bias + tx * 8 + 4);
        bb[0]=c0.x; bb[1]=c0.y; bb[2]=c0.z; bb[3]=c0.w;
        bb[4]=c1.x; bb[5]=c1.y; bb[6]=c1.z; bb[7]=c1.w;
    } else {
        #pragma unroll
        for (int j = 0; j < 8; j++) bb[j] = 0.f;
    }

    #pragma unroll
    for (int i = 0; i < 8; i++) {
        int r = row0 + ty * 8 + i;
        if (r < M) {
            float v[8];
            #pragma unroll
            for (int j = 0; j < 4; j++) {
                float2 p = unp2(acc[i][j]);
                float t0 = p.x + bb[2*j], t1 = p.y + bb[2*j+1];
                v[2*j]   = act ? sspf(t0) : t0;
                v[2*j+1] = act ? sspf(t1) : t1;
            }
            float4* cp = reinterpret_cast<float4*>(C + (size_t)r * 128 + tx * 8);
            cp[0] = make_float4(v[0], v[1], v[2], v[3]);
            cp[1] = make_float4(v[4], v[5], v[6], v[7]);
            if (zbuf) {
                float4* zp = reinterpret_cast<float4*>(zbuf + (size_t)r * 128 + tx * 8);
                zp[0] = make_float4(0.f, 0.f, 0.f, 0.f);
                zp[1] = make_float4(0.f, 0.f, 0.f, 0.f);
            }
        }
    }
}

// ---------------------------------------------------------------------------
// Tensor-core persistent edge kernel. 256 threads = 8 warps (4M x 2N tiling).
// Per 128-edge tile, two K-phases of 64:
//   GEMM1: T[:,p*64..] = ssp(EA @ w1^T + b1)  (bf16 3-term split MMA)
//   GEMM2: D += T_phase @ w2^T                 (bf16 3-term split MMA)
// Then D += b2, staged to smem; gather h[src], scale by cutoff, red4 -> agg.
// ---------------------------------------------------------------------------
__global__ __launch_bounds__(256, 1) void edge_kernel(
    const float* __restrict__ ea, const int* __restrict__ ei,
    const float* __restrict__ ew,
    const float* __restrict__ w1, const float* __restrict__ b1,
    const float* __restrict__ w2, const float* __restrict__ b2,
    const float* __restrict__ h,  float* __restrict__ agg,
    int E, int nTiles)
{
    extern __shared__ char sb[];
    const int tid  = threadIdx.x;
    const int L    = tid & 31;
    const int warp = tid >> 5;
    const int wy   = warp >> 1;        // 0..3 : 32-edge slice
    const int wx   = warp & 1;         // 0..1 : 64-feature slice
    const int m0   = wy * 32;
    // ldmatrix lane addressing (both operands no-trans)
    const int lr   = L & 15;                       // A: row within 16
    const int lk8  = ((L >> 4) & 1) * 8;           // A: k offset 0/8
    const int bn   = (L & 7) + ((L >> 4) & 1) * 8; // B: n row within 16
    const int bk8  = ((L >> 3) & 1) * 8;           // B: k offset 0/8

    float* sBias1 = (float*)(sb + OFF_B1);
    float* sC     = (float*)(sb + OFF_C);
    int*   sSrc   = (int*)(sb + OFF_SRC);
    int*   sDst   = (int*)(sb + OFF_DST);
    float* sD     = (float*)(sb + OFF_D);

    // ---- one-time weight staging (hi/lo split) ----
    for (int idx = tid; idx < 128 * 32; idx += 256) {      // W1: [128][64h pad]
        int f = idx >> 5, kw = idx & 31;
        int g0 = kw * 2, g1 = g0 + 1;
        float v0 = (g0 < NG) ? w1[f * NG + g0] : 0.f;
        float v1 = (g1 < NG) ? w1[f * NG + g1] : 0.f;
        u32 hiw, low; split2(v0, v1, hiw, low);
        *(u32*)(sb + OFF_W1HI + f * 144 + kw * 4) = hiw;
        *(u32*)(sb + OFF_W1LO + f * 144 + kw * 4) = low;
    }
    for (int idx = tid; idx < 128 * 64; idx += 256) {      // W2: [128][128h]
        int f = idx >> 6, kw = idx & 63;
        float2 v = *(const float2*)(w2 + f * 128 + kw * 2);
        u32 hiw, low; split2(v.x, v.y, hiw, low);
        *(u32*)(sb + OFF_W2HI + f * 272 + kw * 4) = hiw;
        *(u32*)(sb + OFF_W2LO + f * 272 + kw * 4) = low;
    }
    if (tid < 128) sBias1[tid] = b1[tid];

    float2 bb2r[8];
    #pragma unroll
    for (int n8 = 0; n8 < 8; n8++)
        bb2r[n8] = *(const float2*)(b2 + wx * 64 + n8 * 8 + 2 * (L & 3));
    __syncthreads();

    for (int t = blockIdx.x; t < nTiles; t += gridDim.x) {
        const int e0 = t * 128;

        // ---- tile staging ----
        if (tid < 128) {
            int e = e0 + tid;
            if (e < E) {
                sSrc[tid] = ei[e];
                sDst[tid] = ei[E + e];
                sC[tid]   = 0.5f * (__cosf(ew[e] * 0.31415926535897932f) + 1.f);
            } else { sSrc[tid] = 0; sDst[tid] = 0; sC[tid] = 0.f; }
        }
        for (int idx = tid; idx < 128 * 32; idx += 256) {  // EA split
            int e = idx >> 5, kw = idx & 31;
            int g0 = kw * 2, g1 = g0 + 1;
            int ge = e0 + e;
            float v0 = (ge < E && g0 < NG) ? ea[(size_t)ge * NG + g0] : 0.f;
            float v1 = (ge < E && g1 < NG) ? ea[(size_t)ge * NG + g1] : 0.f;
            u32 hiw, low; split2(v0, v1, hiw, low);
            *(u32*)(sb + OFF_EAHI + e * 144 + kw * 4) = hiw;
            *(u32*)(sb + OFF_EALO + e * 144 + kw * 4) = low;
        }
        __syncthreads();

        float accD[2][8][4];
        #pragma unroll
        for (int mb = 0; mb < 2; mb++)
            #pragma unroll
            for (int n8 = 0; n8 < 8; n8++)
                #pragma unroll
                for (int r = 0; r < 4; r++) accD[mb][n8][r] = 0.f;

        #pragma unroll
        for (int p = 0; p < 2; p++) {
            // -------- GEMM1: T_phase = ssp(EA @ w1^T + b1), K=64 --------
            float acc1[2][4][4];
            #pragma unroll
            for (int mb = 0; mb < 2; mb++)
                #pragma unroll
                for (int nb = 0; nb < 4; nb++)
                    #pragma unroll
                    for (int r = 0; r < 4; r++) acc1[mb][nb][r] = 0.f;

            #pragma unroll
            for (int ks = 0; ks < 4; ks++) {
                u32 ah[2][4], al[2][4];
                #pragma unroll
                for (int mb = 0; mb < 2; mb++) {
                    u32 ra = (u32)__cvta_generic_to_shared(
                        sb + OFF_EAHI + (m0 + mb * 16 + lr) * 144 + (ks * 16 + lk8) * 2);
                    LDSM_X4(ah[mb], ra);
                    LDSM_X4(al[mb], ra + (OFF_EALO - OFF_EAHI));
                }
                u32 bh[2][4], bl[2][4];
                #pragma unroll
                for (int nq = 0; nq < 2; nq++) {
                    int n0 = p * 64 + wx * 32 + nq * 16;
                    u32 rb = (u32)__cvta_generic_to_shared(
                        sb + OFF_W1HI + (n0 + bn) * 144 + (ks * 16 + bk8) * 2);
                    LDSM_X4(bh[nq], rb);
                    LDSM_X4(bl[nq], rb + (OFF_W1LO - OFF_W1HI));
                }
                #pragma unroll
                for (int mb = 0; mb < 2; mb++)
                    #pragma unroll
                    for (int nb = 0; nb < 4; nb++) {
                        int nq = nb >> 1, rr = (nb & 1) * 2;
                        MMA16816(acc1[mb][nb], ah[mb], bh[nq][rr], bh[nq][rr + 1]);
                        MMA16816(acc1[mb][nb], ah[mb], bl[nq][rr], bl[nq][rr + 1]);
                        MMA16816(acc1[mb][nb], al[mb], bh[nq][rr], bh[nq][rr + 1]);
                    }
            }
            // epilogue: ssp + split -> sT (phase-local k)
            #pragma unroll
            for (int mb = 0; mb < 2; mb++)
                #pragma unroll
                for (int nb = 0; nb < 4; nb++) {
                    int colg = p * 64 + wx * 32 + nb * 8 + 2 * (L & 3);
                    float2 bias = *(float2*)(sBias1 + colg);
                    int tk = wx * 32 + nb * 8 + 2 * (L & 3);
                    int r0 = m0 + mb * 16 + (L >> 2);
                    float v0 = sspf(acc1[mb][nb][0] + bias.x);
                    float v1 = sspf(acc1[mb][nb][1] + bias.y);
                    u32 hiw, low; split2(v0, v1, hiw, low);
                    *(u32*)(sb + OFF_THI + r0 * 144 + tk * 2) = hiw;
                    *(u32*)(sb + OFF_TLO + r0 * 144 + tk * 2) = low;
                    float v2 = sspf(acc1[mb][nb][2] + bias.x);
                    float v3 = sspf(acc1[mb][nb][3] + bias.y);
                    split2(v2, v3, hiw, low);
                    *(u32*)(sb + OFF_THI + (r0 + 8) * 144 + tk * 2) = hiw;
                    *(u32*)(sb + OFF_TLO + (r0 + 8) * 144 + tk * 2) = low;
                }
            __syncthreads();

            // -------- GEMM2 partial: D += T_phase @ w2^T --------
            #pragma unroll
            for (int ks = 0; ks < 4; ks++) {
                u32 ah[2][4], al[2][4];
                #pragma unroll
                for (int mb = 0; mb < 2; mb++) {
                    u32 ra = (u32)__cvta_generic_to_shared(
                        sb + OFF_THI + (m0 + mb * 16 + lr) * 144 + (ks * 16 + lk8) * 2);
                    LDSM_X4(ah[mb], ra);
                    LDSM_X4(al[mb], ra + (OFF_TLO - OFF_THI));
                }
                u32 bh[4][4], bl[4][4];
                #pragma unroll
                for (int nq = 0; nq < 4; nq++) {
                    int n0 = wx * 64 + nq * 16;
                    int k0 = p * 64 + ks * 16;
                    u32 rb = (u32)__cvta_generic_to_shared(
                        sb + OFF_W2HI + (n0 + bn) * 272 + (k0 + bk8) * 2);
                    LDSM_X4(bh[nq], rb);
                    LDSM_X4(bl[nq], rb + (OFF_W2LO - OFF_W2HI));
                }
                #pragma unroll
                for (int mb = 0; mb < 2; mb++)
                    #pragma unroll
                    for (int n8 = 0; n8 < 8; n8++) {
                        int nq = n8 >> 1, rr = (n8 & 1) * 2;
                        MMA16816(accD[mb][n8], ah[mb], bh[nq][rr], bh[nq][rr + 1]);
                        MMA16816(accD[mb][n8], ah[mb], bl[nq][rr], bl[nq][rr + 1]);
                        MMA16816(accD[mb][n8], al[mb], bh[nq][rr], bh[nq][rr + 1]);
                    }
            }
            __syncthreads();
        }

        // ---- D staging (add b2) ----
        #pragma unroll
        for (int mb = 0; mb < 2; mb++)
            #pragma unroll
            for (int n8 = 0; n8 < 8; n8++) {
                int col = wx * 64 + n8 * 8 + 2 * (L & 3);
                int r0  = m0 + mb * 16 + (L >> 2);
                float2 o0 = make_float2(accD[mb][n8][0] + bb2r[n8].x,
                                        accD[mb][n8][1] + bb2r[n8].y);
                *(float2*)(sD + r0 * 132 + col) = o0;
                float2 o1 = make_float2(accD[mb][n8][2] + bb2r[n8].x,
                                        accD[mb][n8][3] + bb2r[n8].y);
                *(float2*)(sD + (r0 + 8) * 132 + col) = o1;
            }
        __syncthreads();

        // ---- scatter epilogue: msg = D * C * h[src] -> red4 agg[dst] ----
        {
            const int tx = tid & 15, ty = tid >> 4;
            #pragma unroll
            for (int i = 0; i < 8; i++) {
                int e = ty * 8 + i;
                int s = sSrc[e], d = sDst[e];
                float c = sC[e];
                float4 d0 = *(float4*)(sD + e * 132 + tx * 8);
                float4 d1 = *(float4*)(sD + e * 132 + tx * 8 + 4);
                const float4* hp = (const float4*)(h + (size_t)s * 128 + tx * 8);
                float4 h0 = hp[0], h1 = hp[1];
                float* ap = agg + (size_t)d * 128 + tx * 8;
                red4(ap,     d0.x * c * h0.x, d0.y * c * h0.y, d0.z * c * h0.z, d0.w * c * h0.w);
                red4(ap + 4, d1.x * c * h1.x, d1.y * c * h1.y, d1.z * c * h1.z, d1.w * c * h1.w);
            }
        }
        __syncthreads();
    }
}

// ---------------------------------------------------------------------------
extern "C" void kernel_launch(void* const* d_in, const int* in_sizes, int n_in,
                              void* d_out, int out_size)
{
    const float* x   = (const float*)d_in[0];
    const int*   ei  = (const int*)  d_in[1];
    const float* ew  = (const float*)d_in[2];
    const float* ea  = (const float*)d_in[3];
    const float* mw1 = (const float*)d_in[4];
    const float* mb1 = (const float*)d_in[5];
    const float* mw2 = (const float*)d_in[6];
    const float* mb2 = (const float*)d_in[7];
    const float* l1w = (const float*)d_in[8];
    const float* l2w = (const float*)d_in[9];
    const float* l2b = (const float*)d_in[10];
    const float* lw  = (const float*)d_in[11];
    const float* lb  = (const float*)d_in[12];
    float* out = (float*)d_out;

    const int N = in_sizes[0] / 128;
    const int E = in_sizes[1] / 2;

    void* p;
    cudaGetSymbolAddress(&p, g_h);   float* h_buf   = (float*)p;
    cudaGetSymbolAddress(&p, g_agg); float* agg_buf = (float*)p;
    cudaGetSymbolAddress(&p, g_h2);  float* h2_buf  = (float*)p;

    int sms = 148;
    cudaDeviceGetAttribute(&sms, cudaDevAttrMultiProcessorCount, 0);

    const size_t smemG = (size_t)2 * 128 * 132 * sizeof(float);   // 135168
    const size_t smemE = SMEM_EDGE;                               // 182272

    cudaFuncSetAttribute(gemm128_kernel, cudaFuncAttributeMaxDynamicSharedMemorySize, (int)smemG);
    cudaFuncSetAttribute(edge_kernel,    cudaFuncAttributeMaxDynamicSharedMemorySize, (int)smemE);

    const int nb     = (N + 127) / 128;
    const int nTiles = (E + 127) / 128;

    gemm128_kernel<<<nb, 256, smemG>>>(x, l1w, nullptr, h_buf, N, 0, agg_buf);
    edge_kernel<<<sms, 256, smemE>>>(ea, ei, ew, mw1, mb1, mw2, mb2, h_buf, agg_buf, E, nTiles);
    gemm128_kernel<<<nb, 256, smemG>>>(agg_buf, l2w, l2b, h2_buf, N, 1, nullptr);
    gemm128_kernel<<<nb, 256, smemG>>>(h2_buf, lw, lb, out, N, 0, nullptr);
}